// round 5
// baseline (speedup 1.0000x reference)
#include <cuda_runtime.h>
#include <stdint.h>

#define T_DIM 20          // timestamp range
#define KEYS  2048        // >= R*T = 2000, padded to pow2
#define EDGE_VEC 4        // int4 vectorization over edges

// ---------------------------------------------------------------------------
// Fused traversal kernel: each block builds the (rel,ts)->batch-bitmask table
// in shared memory directly from r_index/timestamp (B<=32 entries), then
// grid-strides over edges with int4 loads of rel/ts. Matched edges (~1.6%)
// gather head/tail/weight/h_prob and scatter via integer atomicMax (valid
// because all values are >= 0 and output is pre-zeroed).
// ---------------------------------------------------------------------------
__global__ void traverse_kernel(const float* __restrict__ h_prob,
                                const float* __restrict__ edge_weight,
                                const int*   __restrict__ edge_head,
                                const int*   __restrict__ edge_tail,
                                const int*   __restrict__ edge_rel,
                                const int*   __restrict__ edge_ts,
                                const int*   __restrict__ r_index,
                                const int*   __restrict__ timestamp,
                                float* __restrict__ out,
                                int E, int N, int B) {
    __shared__ unsigned int s_table[KEYS];
    for (int k = threadIdx.x; k < KEYS; k += blockDim.x)
        s_table[k] = 0u;
    __syncthreads();
    if (threadIdx.x < B) {
        int key = __ldg(r_index + threadIdx.x) * T_DIM + __ldg(timestamp + threadIdx.x);
        atomicOr(&s_table[key], 1u << threadIdx.x);
    }
    __syncthreads();

    int tid    = blockIdx.x * blockDim.x + threadIdx.x;
    int stride = gridDim.x * blockDim.x * EDGE_VEC;
    int E4     = E & ~(EDGE_VEC - 1);   // vectorizable prefix

    for (int e = tid * EDGE_VEC; e < E4; e += stride) {
        int4 r4 = *reinterpret_cast<const int4*>(edge_rel + e);
        int4 t4 = *reinterpret_cast<const int4*>(edge_ts  + e);
        int rr[4] = {r4.x, r4.y, r4.z, r4.w};
        int tt[4] = {t4.x, t4.y, t4.z, t4.w};
        #pragma unroll
        for (int j = 0; j < EDGE_VEC; j++) {
            unsigned int m = s_table[rr[j] * T_DIM + tt[j]];
            if (m) {
                int   h  = __ldg(edge_head  + e + j);
                int   t  = __ldg(edge_tail  + e + j);
                float we = __ldg(edge_weight + e + j);
                do {
                    int b = __ffs(m) - 1;
                    m &= m - 1;
                    float v = h_prob[b * N + h] * we;
                    atomicMax(reinterpret_cast<int*>(out + b * N + t),
                              __float_as_int(v));
                } while (m);
            }
        }
    }
    // scalar tail (E not multiple of 4)
    for (int e = E4 + tid; e < E; e += gridDim.x * blockDim.x) {
        unsigned int m = s_table[edge_rel[e] * T_DIM + edge_ts[e]];
        if (m) {
            int   h  = edge_head[e];
            int   t  = edge_tail[e];
            float we = edge_weight[e];
            do {
                int b = __ffs(m) - 1;
                m &= m - 1;
                float v = h_prob[b * N + h] * we;
                atomicMax(reinterpret_cast<int*>(out + b * N + t),
                          __float_as_int(v));
            } while (m);
        }
    }
}

// ---------------------------------------------------------------------------
// Launch
// Inputs (metadata order):
//  0 h_prob      [B*N] f32
//  1 edge_weight [E]   f32
//  2 edge_head   [E]   i32
//  3 edge_tail   [E]   i32
//  4 edge_rel    [E]   i32
//  5 edge_ts     [E]   i32
//  6 r_index     [B]   i32
//  7 timestamp   [B]   i32
// ---------------------------------------------------------------------------
extern "C" void kernel_launch(void* const* d_in, const int* in_sizes, int n_in,
                              void* d_out, int out_size) {
    const float* h_prob      = (const float*)d_in[0];
    const float* edge_weight = (const float*)d_in[1];
    const int*   edge_head   = (const int*)  d_in[2];
    const int*   edge_tail   = (const int*)  d_in[3];
    const int*   edge_rel    = (const int*)  d_in[4];
    const int*   edge_ts     = (const int*)  d_in[5];
    const int*   r_index     = (const int*)  d_in[6];
    const int*   timestamp   = (const int*)  d_in[7];
    float*       out         = (float*)d_out;

    int E = in_sizes[1];
    int B = in_sizes[6];
    int N = out_size / B;

    // 1) zero output via HW memset (one graph node, no SM launch)
    cudaMemsetAsync(out, 0, (size_t)out_size * sizeof(float), 0);

    // 2) fused table-build + traversal
    int threads = 256;
    int work_items = (E + EDGE_VEC - 1) / EDGE_VEC;
    int blocks = (work_items + threads - 1) / threads;
    if (blocks > 8192) blocks = 8192;
    if (blocks < 1) blocks = 1;
    traverse_kernel<<<blocks, threads>>>(h_prob, edge_weight, edge_head,
                                         edge_tail, edge_rel, edge_ts,
                                         r_index, timestamp,
                                         out, E, N, B);
}

// round 6
// speedup vs baseline: 1.1657x; 1.1657x over previous
#include <cuda_runtime.h>
#include <stdint.h>

#define T_DIM 20          // timestamp range
#define KEYS  2048        // >= R*T = 2000, padded to pow2
#define EDGE_VEC 8        // edges per thread per iteration (2x int4)

// ---------------------------------------------------------------------------
// Fused traversal kernel, sized so the ENTIRE grid is one resident wave:
// every block builds the (rel,ts)->batch-bitmask table in shared memory once
// (concurrently across blocks), then each thread processes one 8-edge chunk
// with 4 independent LDG.128 in flight. Matched edges (~1.6%) gather
// head/tail/weight/h_prob and scatter via integer atomicMax (valid: all
// values >= 0, output pre-zeroed).
// ---------------------------------------------------------------------------
__global__ void __launch_bounds__(256)
traverse_kernel(const float* __restrict__ h_prob,
                const float* __restrict__ edge_weight,
                const int*   __restrict__ edge_head,
                const int*   __restrict__ edge_tail,
                const int*   __restrict__ edge_rel,
                const int*   __restrict__ edge_ts,
                const int*   __restrict__ r_index,
                const int*   __restrict__ timestamp,
                float* __restrict__ out,
                int E, int N, int B) {
    __shared__ unsigned int s_table[KEYS];

    // Hoist key loads so their latency overlaps the table zeroing.
    int my_key = -1;
    if (threadIdx.x < B)
        my_key = __ldg(r_index + threadIdx.x) * T_DIM + __ldg(timestamp + threadIdx.x);

    // Zero table with 128-bit stores: 2048 words / 256 threads = 2 uint4/thread
    uint4* t4p = reinterpret_cast<uint4*>(s_table);
    #pragma unroll
    for (int k = 0; k < KEYS / 4 / 256; k++)
        t4p[threadIdx.x + k * 256] = make_uint4(0u, 0u, 0u, 0u);
    __syncthreads();
    if (my_key >= 0)
        atomicOr(&s_table[my_key], 1u << threadIdx.x);
    __syncthreads();

    int tid    = blockIdx.x * blockDim.x + threadIdx.x;
    int stride = gridDim.x * blockDim.x * EDGE_VEC;
    int E8     = E & ~(EDGE_VEC - 1);   // vectorizable prefix

    for (int e = tid * EDGE_VEC; e < E8; e += stride) {
        // 4 independent 128-bit loads in flight
        int4 r4a = *reinterpret_cast<const int4*>(edge_rel + e);
        int4 r4b = *reinterpret_cast<const int4*>(edge_rel + e + 4);
        int4 t4a = *reinterpret_cast<const int4*>(edge_ts  + e);
        int4 t4b = *reinterpret_cast<const int4*>(edge_ts  + e + 4);
        int rr[8] = {r4a.x, r4a.y, r4a.z, r4a.w, r4b.x, r4b.y, r4b.z, r4b.w};
        int tt[8] = {t4a.x, t4a.y, t4a.z, t4a.w, t4b.x, t4b.y, t4b.z, t4b.w};
        #pragma unroll
        for (int j = 0; j < EDGE_VEC; j++) {
            unsigned int m = s_table[rr[j] * T_DIM + tt[j]];
            if (m) {
                int   h  = __ldg(edge_head  + e + j);
                int   t  = __ldg(edge_tail  + e + j);
                float we = __ldg(edge_weight + e + j);
                do {
                    int b = __ffs(m) - 1;
                    m &= m - 1;
                    float v = h_prob[b * N + h] * we;
                    atomicMax(reinterpret_cast<int*>(out + b * N + t),
                              __float_as_int(v));
                } while (m);
            }
        }
    }
    // scalar tail (E not multiple of 8)
    for (int e = E8 + tid; e < E; e += gridDim.x * blockDim.x) {
        unsigned int m = s_table[edge_rel[e] * T_DIM + edge_ts[e]];
        if (m) {
            int   h  = edge_head[e];
            int   t  = edge_tail[e];
            float we = edge_weight[e];
            do {
                int b = __ffs(m) - 1;
                m &= m - 1;
                float v = h_prob[b * N + h] * we;
                atomicMax(reinterpret_cast<int*>(out + b * N + t),
                          __float_as_int(v));
            } while (m);
        }
    }
}

// ---------------------------------------------------------------------------
// Launch
// Inputs (metadata order):
//  0 h_prob      [B*N] f32
//  1 edge_weight [E]   f32
//  2 edge_head   [E]   i32
//  3 edge_tail   [E]   i32
//  4 edge_rel    [E]   i32
//  5 edge_ts     [E]   i32
//  6 r_index     [B]   i32
//  7 timestamp   [B]   i32
// ---------------------------------------------------------------------------
extern "C" void kernel_launch(void* const* d_in, const int* in_sizes, int n_in,
                              void* d_out, int out_size) {
    const float* h_prob      = (const float*)d_in[0];
    const float* edge_weight = (const float*)d_in[1];
    const int*   edge_head   = (const int*)  d_in[2];
    const int*   edge_tail   = (const int*)  d_in[3];
    const int*   edge_rel    = (const int*)  d_in[4];
    const int*   edge_ts     = (const int*)  d_in[5];
    const int*   r_index     = (const int*)  d_in[6];
    const int*   timestamp   = (const int*)  d_in[7];
    float*       out         = (float*)d_out;

    int E = in_sizes[1];
    int B = in_sizes[6];
    int N = out_size / B;

    // 1) zero output via HW memset (one graph node, no SM launch)
    cudaMemsetAsync(out, 0, (size_t)out_size * sizeof(float), 0);

    // 2) fused table-build + traversal: single resident wave
    int threads = 256;
    long long chunk = (long long)threads * EDGE_VEC;
    int blocks = (int)((E + chunk - 1) / chunk);   // E=1e6 -> 489 blocks
    if (blocks < 1) blocks = 1;
    traverse_kernel<<<blocks, threads>>>(h_prob, edge_weight, edge_head,
                                         edge_tail, edge_rel, edge_ts,
                                         r_index, timestamp,
                                         out, E, N, B);
}

// round 8
// speedup vs baseline: 1.2226x; 1.0488x over previous
#include <cuda_runtime.h>
#include <stdint.h>

#define T_DIM 20          // timestamp range
#define KEYS  2048        // >= R*T = 2000, padded to pow2
#define EDGE_VEC 4        // edges per thread (one int4 pair)

// ---------------------------------------------------------------------------
// Fused traversal: each thread PREFETCHES its 4-edge chunk (rel+ts int4) so
// the DRAM latency overlaps the per-block shared-table build. Then masks are
// looked up (independent LDS), matched edges' head/tail/weight are loaded as
// a batch of independent LDGs, and results scatter via integer atomicMax
// (valid: all values >= 0, output pre-zeroed by a memset graph node).
// ---------------------------------------------------------------------------
__global__ void __launch_bounds__(256)
traverse_kernel(const float* __restrict__ h_prob,
                const float* __restrict__ edge_weight,
                const int*   __restrict__ edge_head,
                const int*   __restrict__ edge_tail,
                const int*   __restrict__ edge_rel,
                const int*   __restrict__ edge_ts,
                const int*   __restrict__ r_index,
                const int*   __restrict__ timestamp,
                float* __restrict__ out,
                int E, int N, int B) {
    __shared__ unsigned int s_table[KEYS];

    const int tid = blockIdx.x * blockDim.x + threadIdx.x;
    const int E4  = E & ~(EDGE_VEC - 1);
    const int e   = tid * EDGE_VEC;

    // ---- 1) Prefetch edge data FIRST: loads fly while we build the table.
    int4 r4 = make_int4(0, 0, 0, 0);
    int4 t4 = make_int4(0, 0, 0, 0);
    const bool have_chunk = (e < E4);
    if (have_chunk) {
        r4 = *reinterpret_cast<const int4*>(edge_rel + e);
        t4 = *reinterpret_cast<const int4*>(edge_ts  + e);
    }

    // Key loads for the table (2 cache lines, L2-resident after first block)
    int my_key = -1;
    if (threadIdx.x < B)
        my_key = __ldg(r_index + threadIdx.x) * T_DIM + __ldg(timestamp + threadIdx.x);

    // ---- 2) Build shared table (overlapped with the in-flight prefetch).
    uint4* t4p = reinterpret_cast<uint4*>(s_table);
    #pragma unroll
    for (int k = 0; k < KEYS / 4 / 256; k++)
        t4p[threadIdx.x + k * 256] = make_uint4(0u, 0u, 0u, 0u);
    __syncthreads();
    if (my_key >= 0)
        atomicOr(&s_table[my_key], 1u << threadIdx.x);
    __syncthreads();

    // ---- 3) Mask lookup (4 independent LDS), then batched sparse gather.
    if (have_chunk) {
        int rr[4] = {r4.x, r4.y, r4.z, r4.w};
        int tt[4] = {t4.x, t4.y, t4.z, t4.w};
        unsigned int m[4];
        #pragma unroll
        for (int j = 0; j < 4; j++)
            m[j] = s_table[rr[j] * T_DIM + tt[j]];

        unsigned int any = m[0] | m[1] | m[2] | m[3];
        if (any) {
            // Batch all matched-edge loads: independent LDGs in flight together
            int   h[4], t[4];
            float w[4];
            #pragma unroll
            for (int j = 0; j < 4; j++) {
                if (m[j]) {
                    h[j] = __ldg(edge_head  + e + j);
                    t[j] = __ldg(edge_tail  + e + j);
                    w[j] = __ldg(edge_weight + e + j);
                }
            }
            #pragma unroll
            for (int j = 0; j < 4; j++) {
                unsigned int mj = m[j];
                while (mj) {
                    int b = __ffs(mj) - 1;
                    mj &= mj - 1;
                    float v = __ldg(h_prob + b * N + h[j]) * w[j];
                    atomicMax(reinterpret_cast<int*>(out + b * N + t[j]),
                              __float_as_int(v));
                }
            }
        }
    }

    // ---- 4) Scalar tail (E not a multiple of 4) — handled by low tids.
    for (int es = E4 + tid; es < E; es += gridDim.x * blockDim.x) {
        unsigned int mm = s_table[edge_rel[es] * T_DIM + edge_ts[es]];
        while (mm) {
            int b = __ffs(mm) - 1;
            mm &= mm - 1;
            float v = __ldg(h_prob + b * N + edge_head[es]) * edge_weight[es];
            atomicMax(reinterpret_cast<int*>(out + b * N + edge_tail[es]),
                      __float_as_int(v));
        }
    }
}

// ---------------------------------------------------------------------------
// Launch
// Inputs (metadata order):
//  0 h_prob      [B*N] f32
//  1 edge_weight [E]   f32
//  2 edge_head   [E]   i32
//  3 edge_tail   [E]   i32
//  4 edge_rel    [E]   i32
//  5 edge_ts     [E]   i32
//  6 r_index     [B]   i32
//  7 timestamp   [B]   i32
// ---------------------------------------------------------------------------
extern "C" void kernel_launch(void* const* d_in, const int* in_sizes, int n_in,
                              void* d_out, int out_size) {
    const float* h_prob      = (const float*)d_in[0];
    const float* edge_weight = (const float*)d_in[1];
    const int*   edge_head   = (const int*)  d_in[2];
    const int*   edge_tail   = (const int*)  d_in[3];
    const int*   edge_rel    = (const int*)  d_in[4];
    const int*   edge_ts     = (const int*)  d_in[5];
    const int*   r_index     = (const int*)  d_in[6];
    const int*   timestamp   = (const int*)  d_in[7];
    float*       out         = (float*)d_out;

    int E = in_sizes[1];
    int B = in_sizes[6];
    int N = out_size / B;

    // 1) zero output via HW memset (one graph node, no SM launch)
    cudaMemsetAsync(out, 0, (size_t)out_size * sizeof(float), 0);

    // 2) fused table-build + traversal: one 4-edge chunk per thread
    int threads = 256;
    long long chunk = (long long)threads * EDGE_VEC;
    int blocks = (int)((E + chunk - 1) / chunk);   // E=1e6 -> 977 blocks
    if (blocks < 1) blocks = 1;
    traverse_kernel<<<blocks, threads>>>(h_prob, edge_weight, edge_head,
                                         edge_tail, edge_rel, edge_ts,
                                         r_index, timestamp,
                                         out, E, N, B);
}